// round 7
// baseline (speedup 1.0000x reference)
#include <cuda_runtime.h>
#include <stdint.h>
#include <math_constants.h>

#define NBINS       256
#define N_IMG       48
#define IMG_PIX     (1024*1024)
#define TOTAL       (N_IMG*IMG_PIX)
#define TOTAL_V4    (TOTAL/4)                // 12,582,912
#define IMG_V4      (IMG_PIX/4)              // 262144 = 2^18
#define HIST_CHUNKS 32
#define VEC_PER_BLOCK (IMG_V4/HIST_CHUNKS)   // 8192

#define MM_BLOCKS   1536                     // minmax: 1536*256*32 == TOTAL_V4
#define TH_BLOCKS   (TOTAL_V4/512)           // thresh: 2 float4/thread -> 24576
#define HALF_V4     (TOTAL_V4/2)             // 6,291,456

// Persistent scratch, re-armed at the end of every launch sequence (k_thresh)
// so each graph replay sees identical initial state.
__device__ unsigned int g_min_m = 0xFFFFFFFFu;   // monotone-mapped float bits
__device__ unsigned int g_max_m = 0u;
__device__ unsigned int g_hist[N_IMG * NBINS];   // zero-init at load
__device__ unsigned int g_cnt[N_IMG];            // per-image completion counters
__device__ float        g_thresh[N_IMG];

__device__ __forceinline__ unsigned int fmap(float f) {
    unsigned int u = __float_as_uint(f);
    return (u & 0x80000000u) ? ~u : (u | 0x80000000u);
}
__device__ __forceinline__ float funmap(unsigned int m) {
    unsigned int u = (m & 0x80000000u) ? (m ^ 0x80000000u) : ~m;
    return __uint_as_float(u);
}

// ---------------- pass 1: global min/max — MLP=4 batched loads ---------------
__global__ void k_minmax(const float4* __restrict__ x) {
    const int stride = MM_BLOCKS * 256;              // 393216
    int i = blockIdx.x * 256 + threadIdx.x;
    float mn0 =  CUDART_INF_F, mn1 =  CUDART_INF_F, mn2 =  CUDART_INF_F, mn3 =  CUDART_INF_F;
    float mx0 = -CUDART_INF_F, mx1 = -CUDART_INF_F, mx2 = -CUDART_INF_F, mx3 = -CUDART_INF_F;

    #pragma unroll 1
    for (int k = 0; k < 8; k++, i += 4 * stride) {
        float4 a = x[i];
        float4 b = x[i +     stride];
        float4 c = x[i + 2 * stride];
        float4 d = x[i + 3 * stride];
        mn0 = fminf(mn0, fminf(fminf(a.x, a.y), fminf(a.z, a.w)));
        mx0 = fmaxf(mx0, fmaxf(fmaxf(a.x, a.y), fmaxf(a.z, a.w)));
        mn1 = fminf(mn1, fminf(fminf(b.x, b.y), fminf(b.z, b.w)));
        mx1 = fmaxf(mx1, fmaxf(fmaxf(b.x, b.y), fmaxf(b.z, b.w)));
        mn2 = fminf(mn2, fminf(fminf(c.x, c.y), fminf(c.z, c.w)));
        mx2 = fmaxf(mx2, fmaxf(fmaxf(c.x, c.y), fmaxf(c.z, c.w)));
        mn3 = fminf(mn3, fminf(fminf(d.x, d.y), fminf(d.z, d.w)));
        mx3 = fmaxf(mx3, fmaxf(fmaxf(d.x, d.y), fmaxf(d.z, d.w)));
    }
    float mn = fminf(fminf(mn0, mn1), fminf(mn2, mn3));
    float mx = fmaxf(fmaxf(mx0, mx1), fmaxf(mx2, mx3));
    #pragma unroll
    for (int o = 16; o; o >>= 1) {
        mn = fminf(mn, __shfl_down_sync(0xffffffffu, mn, o));
        mx = fmaxf(mx, __shfl_down_sync(0xffffffffu, mx, o));
    }
    __shared__ float smn[8], smx[8];
    int w = threadIdx.x >> 5, l = threadIdx.x & 31;
    if (l == 0) { smn[w] = mn; smx[w] = mx; }
    __syncthreads();
    if (threadIdx.x == 0) {
        #pragma unroll
        for (int j = 1; j < 8; j++) { mn = fminf(mn, smn[j]); mx = fmaxf(mx, smx[j]); }
        atomicMin(&g_min_m, fmap(mn));
        atomicMax(&g_max_m, fmap(mx));
    }
}

// ------- pass 2: per-image histogram (MLP=2) + fused Otsu in last block ------
__global__ void k_hist(const float4* __restrict__ x) {
    __shared__ unsigned int sh[8 * NBINS];
    int tid = threadIdx.x;
    #pragma unroll
    for (int i = tid; i < 8 * NBINS; i += 256) sh[i] = 0u;
    __syncthreads();

    float mn = funmap(g_min_m);
    float mx = funmap(g_max_m);
    float scale = 256.0f / (mx - mn);

    int img   = blockIdx.x / HIST_CHUNKS;
    int chunk = blockIdx.x % HIST_CHUNKS;
    const float4* base = x + (size_t)img * IMG_V4 + (size_t)chunk * VEC_PER_BLOCK;

    unsigned int* myh = sh + ((tid >> 5) << 8);

    // VEC_PER_BLOCK = 8192 -> 16 iterations of 2 batched loads per thread
    #pragma unroll 2
    for (int i = tid; i < VEC_PER_BLOCK; i += 512) {
        float4 v = base[i];
        float4 u = base[i + 256];
        // exact reference arithmetic: (x - mn) * scale, trunc, clamp
        int b0 = min(max((int)((v.x - mn) * scale), 0), 255);
        int b1 = min(max((int)((v.y - mn) * scale), 0), 255);
        int b2 = min(max((int)((v.z - mn) * scale), 0), 255);
        int b3 = min(max((int)((v.w - mn) * scale), 0), 255);
        int c0 = min(max((int)((u.x - mn) * scale), 0), 255);
        int c1 = min(max((int)((u.y - mn) * scale), 0), 255);
        int c2 = min(max((int)((u.z - mn) * scale), 0), 255);
        int c3 = min(max((int)((u.w - mn) * scale), 0), 255);
        atomicAdd(&myh[b0], 1u);
        atomicAdd(&myh[b1], 1u);
        atomicAdd(&myh[b2], 1u);
        atomicAdd(&myh[b3], 1u);
        atomicAdd(&myh[c0], 1u);
        atomicAdd(&myh[c1], 1u);
        atomicAdd(&myh[c2], 1u);
        atomicAdd(&myh[c3], 1u);
    }
    __syncthreads();

    unsigned int s = 0;
    #pragma unroll
    for (int c = 0; c < 8; c++) s += sh[(c << 8) + tid];
    atomicAdd(&g_hist[img * NBINS + tid], s);

    // ---- completion protocol: last block for this image computes Otsu ----
    __shared__ unsigned int s_last;
    __threadfence();                       // make our RED visible before count
    if (tid == 0)
        s_last = (atomicAdd(&g_cnt[img], 1u) == HIST_CHUNKS - 1) ? 1u : 0u;
    __syncthreads();
    if (!s_last) return;

    // ---- Otsu for this image (volatile reads: coherent at L2 with REDs) ----
    __shared__ float h[NBINS], W[NBINS], S[NBINS], bv[NBINS];
    __shared__ int bi[NBINS];
    int t = tid;
    volatile const unsigned int* gh = g_hist + img * NBINS;
    h[t] = (float)gh[t] * (1.0f / (float)IMG_PIX);
    __syncthreads();

    if (t == 0) {   // sequential cumsum order; loads batched so chain is FADD-only
        float cw = 0.0f, cs = 0.0f;
        #pragma unroll 4
        for (int i = 0; i < NBINS; i += 8) {
            float v0 = h[i+0], v1 = h[i+1], v2 = h[i+2], v3 = h[i+3];
            float v4 = h[i+4], v5 = h[i+5], v6 = h[i+6], v7 = h[i+7];
            cw += v0; W[i+0] = cw; cs += v0 * (float)(i+0); S[i+0] = cs;
            cw += v1; W[i+1] = cw; cs += v1 * (float)(i+1); S[i+1] = cs;
            cw += v2; W[i+2] = cw; cs += v2 * (float)(i+2); S[i+2] = cs;
            cw += v3; W[i+3] = cw; cs += v3 * (float)(i+3); S[i+3] = cs;
            cw += v4; W[i+4] = cw; cs += v4 * (float)(i+4); S[i+4] = cs;
            cw += v5; W[i+5] = cw; cs += v5 * (float)(i+5); S[i+5] = cs;
            cw += v6; W[i+6] = cw; cs += v6 * (float)(i+6); S[i+6] = cs;
            cw += v7; W[i+7] = cw; cs += v7 * (float)(i+7); S[i+7] = cs;
        }
    }
    __syncthreads();

    float w_bg = W[t], s_bg = S[t];
    float total = S[NBINS - 1];
    float w_fg = 1.0f - w_bg;
    float var;
    if (w_bg > 0.0f && w_fg > 0.0f) {
        float mb = s_bg / w_bg;
        float mf = (total - s_bg) / w_fg;
        float d = mb - mf;
        var = w_bg * w_fg * (d * d);
    } else {
        var = -CUDART_INF_F;
    }
    bv[t] = var; bi[t] = t;
    __syncthreads();

    #pragma unroll
    for (int o = 128; o; o >>= 1) {    // argmax, first index wins ties
        if (t < o) {
            float vo = bv[t + o]; int io = bi[t + o];
            if (vo > bv[t] || (vo == bv[t] && io < bi[t])) { bv[t] = vo; bi[t] = io; }
        }
        __syncthreads();
    }
    if (t == 0) {
        float span = mx - mn;
        g_thresh[img] = mn + span * ((float)(bi[0] + 1) * (1.0f / 256.0f));
    }
}

// ---------------- pass 3: thresholded write-out, 2 float4/thread -------------
__global__ void k_thresh(const float4* __restrict__ x, float4* __restrict__ out) {
    int j = blockIdx.x * 256 + threadIdx.x;       // 0 .. HALF_V4-1
    int i0 = j;
    int i1 = j + HALF_V4;

    float thr0 = __ldg(&g_thresh[i0 >> 18]);      // IMG_V4 = 2^18
    float thr1 = __ldg(&g_thresh[i1 >> 18]);
    float4 v0 = x[i0];
    float4 v1 = x[i1];
    float4 o0, o1;
    o0.x = (v0.x <= thr0) ? 0.0f : v0.x;
    o0.y = (v0.y <= thr0) ? 0.0f : v0.y;
    o0.z = (v0.z <= thr0) ? 0.0f : v0.z;
    o0.w = (v0.w <= thr0) ? 0.0f : v0.w;
    o1.x = (v1.x <= thr1) ? 0.0f : v1.x;
    o1.y = (v1.y <= thr1) ? 0.0f : v1.y;
    o1.z = (v1.z <= thr1) ? 0.0f : v1.z;
    o1.w = (v1.w <= thr1) ? 0.0f : v1.w;
    __stcs(&out[i0], o0);
    __stcs(&out[i1], o1);

    // Re-arm scratch for the NEXT graph replay (nothing later in this launch
    // sequence reads these).
    if (j < N_IMG * NBINS) g_hist[j] = 0u;
    if (j < N_IMG)         g_cnt[j]  = 0u;
    if (j == 0) { g_min_m = 0xFFFFFFFFu; g_max_m = 0u; }
}

extern "C" void kernel_launch(void* const* d_in, const int* in_sizes, int n_in,
                              void* d_out, int out_size) {
    const float4* x = (const float4*)d_in[0];
    float4* out = (float4*)d_out;
    (void)in_sizes; (void)n_in; (void)out_size;

    k_minmax<<<MM_BLOCKS, 256>>>(x);               // 1536 blocks, MLP=4
    k_hist<<<N_IMG * HIST_CHUNKS, 256>>>(x);       // 1536 blocks + fused otsu
    k_thresh<<<TH_BLOCKS, 256>>>(x, out);          // 24576 blocks, 2 f4/thread
}

// round 8
// speedup vs baseline: 1.0289x; 1.0289x over previous
#include <cuda_runtime.h>
#include <stdint.h>
#include <math_constants.h>

#define NBINS       256
#define N_IMG       48
#define IMG_PIX     (1024*1024)
#define TOTAL       (N_IMG*IMG_PIX)
#define TOTAL_V4    (TOTAL/4)                // 12,582,912
#define IMG_V4      (IMG_PIX/4)              // 262144 = 2^18
#define HIST_CHUNKS 16
#define VEC_PER_BLOCK (IMG_V4/HIST_CHUNKS)   // 16384

#define MM_BLOCKS   1024                     // single wave; 1024*256*48 == TOTAL_V4
#define TH_BLOCKS   (TOTAL_V4/512)           // thresh: 2 float4/thread -> 24576
#define HALF_V4     (TOTAL_V4/2)             // 6,291,456

// Persistent scratch, re-armed at the end of every launch sequence (k_thresh)
// so each graph replay sees identical initial state.
__device__ unsigned int g_min_m = 0xFFFFFFFFu;   // monotone-mapped float bits
__device__ unsigned int g_max_m = 0u;
__device__ unsigned int g_hist[N_IMG * NBINS];   // zero-init at load
__device__ float        g_thresh[N_IMG];

__device__ __forceinline__ unsigned int fmap(float f) {
    unsigned int u = __float_as_uint(f);
    return (u & 0x80000000u) ? ~u : (u | 0x80000000u);
}
__device__ __forceinline__ float funmap(unsigned int m) {
    unsigned int u = (m & 0x80000000u) ? (m ^ 0x80000000u) : ~m;
    return __uint_as_float(u);
}

// -------- pass 1: global min/max — single wave, MLP=4 batched loads ----------
__global__ void k_minmax(const float4* __restrict__ x) {
    const int stride = MM_BLOCKS * 256;              // 262144
    int i = blockIdx.x * 256 + threadIdx.x;
    float mn0 =  CUDART_INF_F, mn1 =  CUDART_INF_F, mn2 =  CUDART_INF_F, mn3 =  CUDART_INF_F;
    float mx0 = -CUDART_INF_F, mx1 = -CUDART_INF_F, mx2 = -CUDART_INF_F, mx3 = -CUDART_INF_F;

    #pragma unroll 1
    for (int k = 0; k < 12; k++, i += 4 * stride) {   // 12*4 = 48 loads/thread
        float4 a = x[i];
        float4 b = x[i +     stride];
        float4 c = x[i + 2 * stride];
        float4 d = x[i + 3 * stride];
        mn0 = fminf(mn0, fminf(fminf(a.x, a.y), fminf(a.z, a.w)));
        mx0 = fmaxf(mx0, fmaxf(fmaxf(a.x, a.y), fmaxf(a.z, a.w)));
        mn1 = fminf(mn1, fminf(fminf(b.x, b.y), fminf(b.z, b.w)));
        mx1 = fmaxf(mx1, fmaxf(fmaxf(b.x, b.y), fmaxf(b.z, b.w)));
        mn2 = fminf(mn2, fminf(fminf(c.x, c.y), fminf(c.z, c.w)));
        mx2 = fmaxf(mx2, fmaxf(fmaxf(c.x, c.y), fmaxf(c.z, c.w)));
        mn3 = fminf(mn3, fminf(fminf(d.x, d.y), fminf(d.z, d.w)));
        mx3 = fmaxf(mx3, fmaxf(fmaxf(d.x, d.y), fmaxf(d.z, d.w)));
    }
    float mn = fminf(fminf(mn0, mn1), fminf(mn2, mn3));
    float mx = fmaxf(fmaxf(mx0, mx1), fmaxf(mx2, mx3));
    #pragma unroll
    for (int o = 16; o; o >>= 1) {
        mn = fminf(mn, __shfl_down_sync(0xffffffffu, mn, o));
        mx = fmaxf(mx, __shfl_down_sync(0xffffffffu, mx, o));
    }
    __shared__ float smn[8], smx[8];
    int w = threadIdx.x >> 5, l = threadIdx.x & 31;
    if (l == 0) { smn[w] = mn; smx[w] = mx; }
    __syncthreads();
    if (threadIdx.x == 0) {
        #pragma unroll
        for (int j = 1; j < 8; j++) { mn = fminf(mn, smn[j]); mx = fmaxf(mx, smx[j]); }
        atomicMin(&g_min_m, fmap(mn));
        atomicMax(&g_max_m, fmap(mx));
    }
}

// ------ pass 2: per-image histogram — single wave (768 blocks), MLP=2 --------
__global__ void k_hist(const float4* __restrict__ x) {
    __shared__ unsigned int sh[8 * NBINS];
    int tid = threadIdx.x;
    #pragma unroll
    for (int i = tid; i < 8 * NBINS; i += 256) sh[i] = 0u;
    __syncthreads();

    float mn = funmap(g_min_m);
    float mx = funmap(g_max_m);
    float scale = 256.0f / (mx - mn);

    int img   = blockIdx.x / HIST_CHUNKS;
    int chunk = blockIdx.x % HIST_CHUNKS;
    const float4* base = x + (size_t)img * IMG_V4 + (size_t)chunk * VEC_PER_BLOCK;

    unsigned int* myh = sh + ((tid >> 5) << 8);

    // VEC_PER_BLOCK = 16384 -> 32 iterations of 2 batched loads per thread
    #pragma unroll 2
    for (int i = tid; i < VEC_PER_BLOCK; i += 512) {
        float4 v = base[i];
        float4 u = base[i + 256];
        // exact reference arithmetic: (x - mn) * scale, trunc, clamp
        int b0 = min(max((int)((v.x - mn) * scale), 0), 255);
        int b1 = min(max((int)((v.y - mn) * scale), 0), 255);
        int b2 = min(max((int)((v.z - mn) * scale), 0), 255);
        int b3 = min(max((int)((v.w - mn) * scale), 0), 255);
        int c0 = min(max((int)((u.x - mn) * scale), 0), 255);
        int c1 = min(max((int)((u.y - mn) * scale), 0), 255);
        int c2 = min(max((int)((u.z - mn) * scale), 0), 255);
        int c3 = min(max((int)((u.w - mn) * scale), 0), 255);
        atomicAdd(&myh[b0], 1u);
        atomicAdd(&myh[b1], 1u);
        atomicAdd(&myh[b2], 1u);
        atomicAdd(&myh[b3], 1u);
        atomicAdd(&myh[c0], 1u);
        atomicAdd(&myh[c1], 1u);
        atomicAdd(&myh[c2], 1u);
        atomicAdd(&myh[c3], 1u);
    }
    __syncthreads();

    unsigned int s = 0;
    #pragma unroll
    for (int c = 0; c < 8; c++) s += sh[(c << 8) + tid];
    atomicAdd(&g_hist[img * NBINS + tid], s);   // RED, scattered, cheap
}

// ---------------- pass 3: Otsu per image (48 tiny blocks) --------------------
__global__ void k_otsu() {
    __shared__ float h[NBINS];
    __shared__ float W[NBINS], S[NBINS];
    __shared__ float bv[NBINS];
    __shared__ int   bi[NBINS];
    int img = blockIdx.x;
    int t = threadIdx.x;

    h[t] = (float)g_hist[img * NBINS + t] * (1.0f / (float)IMG_PIX);
    __syncthreads();

    // sequential cumsum order; loads batched 8-wide so the chain is FADD-only
    if (t == 0) {
        float cw = 0.0f, cs = 0.0f;
        #pragma unroll 4
        for (int i = 0; i < NBINS; i += 8) {
            float v0 = h[i+0], v1 = h[i+1], v2 = h[i+2], v3 = h[i+3];
            float v4 = h[i+4], v5 = h[i+5], v6 = h[i+6], v7 = h[i+7];
            cw += v0; W[i+0] = cw; cs += v0 * (float)(i+0); S[i+0] = cs;
            cw += v1; W[i+1] = cw; cs += v1 * (float)(i+1); S[i+1] = cs;
            cw += v2; W[i+2] = cw; cs += v2 * (float)(i+2); S[i+2] = cs;
            cw += v3; W[i+3] = cw; cs += v3 * (float)(i+3); S[i+3] = cs;
            cw += v4; W[i+4] = cw; cs += v4 * (float)(i+4); S[i+4] = cs;
            cw += v5; W[i+5] = cw; cs += v5 * (float)(i+5); S[i+5] = cs;
            cw += v6; W[i+6] = cw; cs += v6 * (float)(i+6); S[i+6] = cs;
            cw += v7; W[i+7] = cw; cs += v7 * (float)(i+7); S[i+7] = cs;
        }
    }
    __syncthreads();

    float w_bg = W[t], s_bg = S[t];
    float total = S[NBINS - 1];
    float w_fg = 1.0f - w_bg;
    float var;
    if (w_bg > 0.0f && w_fg > 0.0f) {
        float mb = s_bg / w_bg;
        float mf = (total - s_bg) / w_fg;
        float d = mb - mf;
        var = w_bg * w_fg * (d * d);
    } else {
        var = -CUDART_INF_F;
    }
    bv[t] = var; bi[t] = t;
    __syncthreads();

    // argmax, first index wins on ties (matches jnp.argmax)
    #pragma unroll
    for (int o = 128; o; o >>= 1) {
        if (t < o) {
            float vo = bv[t + o]; int io = bi[t + o];
            if (vo > bv[t] || (vo == bv[t] && io < bi[t])) { bv[t] = vo; bi[t] = io; }
        }
        __syncthreads();
    }
    if (t == 0) {
        float mn = funmap(g_min_m), mx = funmap(g_max_m);
        float span = mx - mn;
        g_thresh[img] = mn + span * ((float)(bi[0] + 1) * (1.0f / 256.0f));
    }
}

// ---------------- pass 4: thresholded write-out, 2 float4/thread -------------
__global__ void k_thresh(const float4* __restrict__ x, float4* __restrict__ out) {
    int j = blockIdx.x * 256 + threadIdx.x;       // 0 .. HALF_V4-1
    int i0 = j;
    int i1 = j + HALF_V4;

    float thr0 = __ldg(&g_thresh[i0 >> 18]);      // IMG_V4 = 2^18
    float thr1 = __ldg(&g_thresh[i1 >> 18]);
    float4 v0 = x[i0];
    float4 v1 = x[i1];
    float4 o0, o1;
    o0.x = (v0.x <= thr0) ? 0.0f : v0.x;
    o0.y = (v0.y <= thr0) ? 0.0f : v0.y;
    o0.z = (v0.z <= thr0) ? 0.0f : v0.z;
    o0.w = (v0.w <= thr0) ? 0.0f : v0.w;
    o1.x = (v1.x <= thr1) ? 0.0f : v1.x;
    o1.y = (v1.y <= thr1) ? 0.0f : v1.y;
    o1.z = (v1.z <= thr1) ? 0.0f : v1.z;
    o1.w = (v1.w <= thr1) ? 0.0f : v1.w;
    __stcs(&out[i0], o0);
    __stcs(&out[i1], o1);

    // Re-arm scratch for the NEXT graph replay (nothing later in this launch
    // sequence reads these): zero g_hist, reset min/max identities.
    if (j < N_IMG * NBINS) g_hist[j] = 0u;
    if (j == 0) { g_min_m = 0xFFFFFFFFu; g_max_m = 0u; }
}

extern "C" void kernel_launch(void* const* d_in, const int* in_sizes, int n_in,
                              void* d_out, int out_size) {
    const float4* x = (const float4*)d_in[0];
    float4* out = (float4*)d_out;
    (void)in_sizes; (void)n_in; (void)out_size;

    k_minmax<<<MM_BLOCKS, 256>>>(x);               // 1024 blocks, one wave, MLP=4
    k_hist<<<N_IMG * HIST_CHUNKS, 256>>>(x);       // 768 blocks, one wave
    k_otsu<<<N_IMG, 256>>>();
    k_thresh<<<TH_BLOCKS, 256>>>(x, out);          // 24576 blocks, 2 f4/thread
}